// round 6
// baseline (speedup 1.0000x reference)
#include <cuda_runtime.h>
#include <cuda_fp16.h>
#include <cstdint>
#include <cstddef>

#define NROW   200000
#define CIN    64
#define COUT   64
#define KOFF   27
#define TILE_M 128
#define NTILES ((NROW + TILE_M - 1) / TILE_M)   // 1563
// CTA specialization ratio: tensor if (bid % 23) < 7  -> ~30.4% tensor tiles
#define TDEN 23
#define TNUM 7

typedef unsigned long long u64t;

// ---------------- device scratch ----------------
__device__ __align__(128) __half g_feats16[(NROW + 8) * CIN];   // row NROW = zeros (tensor path)
__device__ __align__(128) float  g_feats32[(NROW + 8) * CIN];   // row NROW = zeros (SIMT path)
__device__ __align__(128) __half g_w16[KOFF * CIN * COUT];      // fp16 [k][cin][cout]
__device__ __align__(128) float  g_wT32[KOFF * COUT * CIN];     // fp32 [k][cout][cin] (transposed)
__device__ int    g_idx2[KOFF * NROW];
__device__ float  g_conv[(size_t)NROW * COUT];
__device__ float  g_partials[NTILES * 128];
__device__ float  g_bn[128];

// ---------------- helpers ----------------
__device__ __forceinline__ uint32_t smem_u32(const void* p) {
    uint32_t a;
    asm("{ .reg .u64 t; cvta.to.shared.u64 t, %1; cvt.u32.u64 %0, t; }" : "=r"(a) : "l"(p));
    return a;
}
__device__ __forceinline__ void cp_async16(uint32_t dst, const void* src) {
    asm volatile("cp.async.cg.shared.global [%0], [%1], 16;" :: "r"(dst), "l"(src));
}
__device__ __forceinline__ void cp_commit() {
    asm volatile("cp.async.commit_group;" ::: "memory");
}
__device__ __forceinline__ void ldmatrix_x4(uint32_t* r, uint32_t addr) {
    asm volatile("ldmatrix.sync.aligned.m8n8.x4.shared.b16 {%0,%1,%2,%3}, [%4];"
                 : "=r"(r[0]), "=r"(r[1]), "=r"(r[2]), "=r"(r[3]) : "r"(addr));
}
__device__ __forceinline__ void ldmatrix_x4_t(uint32_t* r, uint32_t addr) {
    asm volatile("ldmatrix.sync.aligned.m8n8.x4.trans.shared.b16 {%0,%1,%2,%3}, [%4];"
                 : "=r"(r[0]), "=r"(r[1]), "=r"(r[2]), "=r"(r[3]) : "r"(addr));
}
__device__ __forceinline__ void mma16816(float* d, const uint32_t* a, uint32_t b0, uint32_t b1) {
    asm volatile(
        "mma.sync.aligned.m16n8k16.row.col.f32.f16.f16.f32 "
        "{%0,%1,%2,%3}, {%4,%5,%6,%7}, {%8,%9}, {%0,%1,%2,%3};"
        : "+f"(d[0]), "+f"(d[1]), "+f"(d[2]), "+f"(d[3])
        : "r"(a[0]), "r"(a[1]), "r"(a[2]), "r"(a[3]), "r"(b0), "r"(b1));
}

// ---------------- SMEM layout (union of both CTA types) ----------------
// tensor:
#define TA_STRIDE 144
#define TA_STAGE  (128 * TA_STRIDE)   // 18432
#define TB_STRIDE 144
#define TB_STAGE  (64 * TB_STRIDE)    // 9216
#define OFF_TA    0
#define OFF_TB    (2 * TA_STAGE)      // 36864
// SIMT:
#define SA_STRIDE 272                 // 64 f32 + 16B pad; LDS.128 conflict-free
#define SA_STAGE  (128 * SA_STRIDE)   // 34816
#define SW_STRIDE 272
#define SW_STAGE  (64 * SW_STRIDE)    // 17408
#define OFF_SA    0
#define OFF_SW    (2 * SA_STAGE)      // 69632
#define SMEM_BYTES (OFF_SW + 2 * SW_STAGE)  // 104448
// epilogue scratch (after compute, both types): stats [64][129] f32 at 0, PS at 34816
#define OFF_PS    34816

// ---------------- prep kernels ----------------
__global__ void prep_feats_kernel(const float* __restrict__ feats) {
    int i = blockIdx.x * 256 + threadIdx.x;      // one float4
    if (i < NROW * (CIN / 4)) {
        float4 v = reinterpret_cast<const float4*>(feats)[i];
        __half2* dst = reinterpret_cast<__half2*>(g_feats16);
        dst[i * 2]     = __floats2half2_rn(v.x, v.y);
        dst[i * 2 + 1] = __floats2half2_rn(v.z, v.w);
        reinterpret_cast<float4*>(g_feats32)[i] = v;
    } else if (i < NROW * (CIN / 4) + (CIN / 4)) { // zero row at index NROW
        __half2 z = __float2half2_rn(0.0f);
        __half2* dst = reinterpret_cast<__half2*>(g_feats16);
        dst[i * 2]     = z;
        dst[i * 2 + 1] = z;
        reinterpret_cast<float4*>(g_feats32)[i] = make_float4(0.f, 0.f, 0.f, 0.f);
    }
}
__global__ void prep_w_kernel(const float* __restrict__ W) {
    int i = blockIdx.x * 256 + threadIdx.x;
    if (i < KOFF * CIN * COUT) {
        int k  = i / (CIN * COUT);
        int r  = i % (CIN * COUT);
        int ci = r / COUT;
        int co = r % COUT;
        float w = W[i];
        g_w16[i] = __float2half_rn(w);
        g_wT32[(k * COUT + co) * CIN + ci] = w;
    }
}
__global__ void prep_idx_kernel(const int* __restrict__ nbr, const int* __restrict__ mask) {
    int i = blockIdx.x * 256 + threadIdx.x;
    if (i < KOFF * NROW) g_idx2[i] = mask[i] ? nbr[i] : NROW;
}

// ---------------- tensor-CTA loader (256 threads) ----------------
__device__ __forceinline__ void t_load_stage(uint32_t sb, int tid, int m0, int k) {
    int s = k & 1;
    uint32_t abuf = sb + OFF_TA + s * TA_STAGE;
    uint32_t bbuf = sb + OFF_TB + s * TB_STAGE;
    const int* idxk = g_idx2 + k * NROW;
    #pragma unroll
    for (int it = 0; it < 4; it++) {
        int cid = it * 256 + tid;
        int r = cid >> 3, ch = cid & 7;
        int m = m0 + r;
        int src = (m < NROW) ? __ldg(idxk + m) : NROW;
        cp_async16(abuf + (uint32_t)(r * TA_STRIDE + ch * 16),
                   (const char*)g_feats16 + ((size_t)src * (CIN * 2) + ch * 16));
    }
    const char* wsrc = (const char*)g_w16 + (size_t)k * (CIN * COUT * 2);
    #pragma unroll
    for (int it = 0; it < 2; it++) {
        int cid = it * 256 + tid;
        int r = cid >> 3, ch = cid & 7;
        cp_async16(bbuf + (uint32_t)(r * TB_STRIDE + ch * 16), wsrc + r * 128 + ch * 16);
    }
    cp_commit();
}

// ---------------- SIMT-CTA loaders (256 threads) ----------------
__device__ __forceinline__ void s_load_stage(uint32_t sb, int tid, int m0, int k, int buf) {
    uint32_t abuf = sb + OFF_SA + buf * SA_STAGE;
    const int* idxk = g_idx2 + k * NROW;
    int ch = tid & 15;
    #pragma unroll
    for (int it = 0; it < 8; it++) {   // A: 128 rows x 16 chunks of 16B (f32)
        int r = it * 16 + (tid >> 4);
        int m = m0 + r;
        int src = (m < NROW) ? __ldg(idxk + m) : NROW;
        cp_async16(abuf + (uint32_t)(r * SA_STRIDE + ch * 16),
                   (const char*)g_feats32 + ((size_t)src * 256 + ch * 16));
    }
    uint32_t wbuf = sb + OFF_SW + buf * SW_STAGE;
    const char* wsrc = (const char*)g_wT32 + (size_t)k * (COUT * CIN * 4);
    #pragma unroll
    for (int it = 0; it < 4; it++) {   // W^T: 64 couts x 16 chunks of 16B
        int id = it * 256 + tid;
        int co = id >> 4, c16 = id & 15;
        cp_async16(wbuf + (uint32_t)(co * SW_STRIDE + c16 * 16), wsrc + co * 256 + c16 * 16);
    }
    cp_commit();
}

// SIMT compute: partial-pair FFMA2. thread: rows {g,g+32,g+64,g+96}, couts [8cg, 8cg+8)
__device__ __forceinline__ void s_compute(uint32_t sb, int buf, int g, int cg, u64t acc[4][8]) {
    uint32_t abase = sb + OFF_SA + buf * SA_STAGE + (uint32_t)(g * SA_STRIDE);
    uint32_t wbase = sb + OFF_SW + buf * SW_STAGE + (uint32_t)(cg * 8 * SW_STRIDE);
    #pragma unroll 2
    for (int q = 0; q < 16; q++) {           // cin quads (4 f32 = 2 pairs)
        u64t a[4][2];
        #pragma unroll
        for (int m = 0; m < 4; m++) {
            asm volatile("ld.shared.v2.u64 {%0,%1}, [%2];"
                : "=l"(a[m][0]), "=l"(a[m][1])
                : "r"(abase + (uint32_t)(m * 32 * SA_STRIDE + q * 16)));
        }
        #pragma unroll
        for (int h = 0; h < 2; h++) {        // couts in halves of 4
            u64t w[4][2];
            #pragma unroll
            for (int j = 0; j < 4; j++) {
                asm volatile("ld.shared.v2.u64 {%0,%1}, [%2];"
                    : "=l"(w[j][0]), "=l"(w[j][1])
                    : "r"(wbase + (uint32_t)((h * 4 + j) * SW_STRIDE + q * 16)));
            }
            #pragma unroll
            for (int m = 0; m < 4; m++)
                #pragma unroll
                for (int j = 0; j < 4; j++) {
                    asm("fma.rn.f32x2 %0, %1, %2, %0;"
                        : "+l"(acc[m][h * 4 + j]) : "l"(a[m][0]), "l"(w[j][0]));
                    asm("fma.rn.f32x2 %0, %1, %2, %0;"
                        : "+l"(acc[m][h * 4 + j]) : "l"(a[m][1]), "l"(w[j][1]));
                }
        }
    }
}

// ---------------- main kernel: CTA-specialized ----------------
__global__ void __launch_bounds__(256, 2) conv_mma_kernel() {
    extern __shared__ char smem[];
    uint32_t sb = smem_u32(smem);
    int tid = threadIdx.x;
    int m0 = blockIdx.x * TILE_M;
    float* stats = (float*)smem;   // [64][129] f32 (written post-compute)
    bool tensor_cta = (blockIdx.x % TDEN) < TNUM;

    if (tensor_cta) {
        // ============ TENSOR CTA: all 27 offsets, mma.sync ============
        int lane = tid & 31, wid = tid >> 5;
        int warp_m = wid & 3, warp_n = wid >> 2;   // 4x2 warps, warp tile 32x32
        float d[2][4][4];
        #pragma unroll
        for (int i = 0; i < 2; i++)
            #pragma unroll
            for (int j = 0; j < 4; j++)
                #pragma unroll
                for (int l = 0; l < 4; l++) d[i][j][l] = 0.f;

        t_load_stage(sb, tid, m0, 0);
        uint32_t a_off = (uint32_t)((warp_m * 32 + (lane & 15)) * TA_STRIDE + (lane >> 4) * 16);
        uint32_t b_off = (uint32_t)((lane & 15) * TB_STRIDE + warp_n * 64 + (lane >> 4) * 16);

        #pragma unroll 1
        for (int k = 0; k < KOFF; k++) {
            if (k < KOFF - 1) {
                t_load_stage(sb, tid, m0, k + 1);
                asm volatile("cp.async.wait_group 1;" ::: "memory");
            } else {
                asm volatile("cp.async.wait_group 0;" ::: "memory");
            }
            __syncthreads();
            uint32_t abase = sb + OFF_TA + (k & 1) * TA_STAGE + a_off;
            uint32_t bbase = sb + OFF_TB + (k & 1) * TB_STAGE + b_off;
            #pragma unroll
            for (int kk = 0; kk < 4; kk++) {
                uint32_t a0 = abase + kk * 32;
                uint32_t bk = bbase + kk * 16 * TB_STRIDE;
                uint32_t afr[2][4], bfr[2][4];
                ldmatrix_x4(afr[0], a0);
                ldmatrix_x4(afr[1], a0 + 16 * TA_STRIDE);
                ldmatrix_x4_t(bfr[0], bk);
                ldmatrix_x4_t(bfr[1], bk + 32);
                #pragma unroll
                for (int mi = 0; mi < 2; mi++)
                    #pragma unroll
                    for (int nn = 0; nn < 4; nn++)
                        mma16816(d[mi][nn], afr[mi],
                                 bfr[nn >> 1][(nn & 1) * 2], bfr[nn >> 1][(nn & 1) * 2 + 1]);
            }
            __syncthreads();
        }
        {   // write results into stats
            int r0 = warp_m * 32 + (lane >> 2);
            int c0 = warp_n * 32 + (lane & 3) * 2;
            #pragma unroll
            for (int mi = 0; mi < 2; mi++)
                #pragma unroll
                for (int nn = 0; nn < 4; nn++) {
                    int r = r0 + mi * 16;
                    int c = c0 + nn * 8;
                    stats[(c + 0) * 129 + r]     = d[mi][nn][0];
                    stats[(c + 1) * 129 + r]     = d[mi][nn][1];
                    stats[(c + 0) * 129 + r + 8] = d[mi][nn][2];
                    stats[(c + 1) * 129 + r + 8] = d[mi][nn][3];
                }
        }
    } else {
        // ============ SIMT CTA: all 27 offsets, fma.rn.f32x2 ============
        int g = tid & 31;          // row group: rows g + 32m
        int cg = tid >> 5;         // cout group: 8 couts
        u64t acc[4][8];
        #pragma unroll
        for (int m = 0; m < 4; m++)
            #pragma unroll
            for (int j = 0; j < 8; j++) acc[m][j] = 0ull;

        s_load_stage(sb, tid, m0, 0, 0);
        s_load_stage(sb, tid, m0, 1, 1);

        #pragma unroll 1
        for (int k = 0; k < KOFF; k++) {
            if (k < KOFF - 1) asm volatile("cp.async.wait_group 1;" ::: "memory");
            else              asm volatile("cp.async.wait_group 0;" ::: "memory");
            __syncthreads();
            s_compute(sb, k & 1, g, cg, acc);
            __syncthreads();
            if (k + 2 < KOFF) s_load_stage(sb, tid, m0, k + 2, k & 1);
        }
        // horizontal add of partial pairs -> stats
        #pragma unroll
        for (int m = 0; m < 4; m++)
            #pragma unroll
            for (int j = 0; j < 8; j++) {
                uint32_t lo, hi;
                asm("mov.b64 {%0, %1}, %2;" : "=r"(lo), "=r"(hi) : "l"(acc[m][j]));
                stats[(cg * 8 + j) * 129 + (g + 32 * m)] =
                    __uint_as_float(lo) + __uint_as_float(hi);
            }
    }
    __syncthreads();

    // ---------------- common epilogue (256 threads) ----------------
    #pragma unroll
    for (int it = 0; it < 8; it++) {
        int idx = it * 256 + tid;
        int r = idx >> 4, c4 = idx & 15;
        int m = m0 + r;
        if (m < NROW) {
            float4 v;
            v.x = stats[(c4 * 4 + 0) * 129 + r];
            v.y = stats[(c4 * 4 + 1) * 129 + r];
            v.z = stats[(c4 * 4 + 2) * 129 + r];
            v.w = stats[(c4 * 4 + 3) * 129 + r];
            reinterpret_cast<float4*>(g_conv + (size_t)m * COUT)[c4] = v;
        }
    }
    {   // per-tile channel sums, fixed order -> deterministic
        int c = tid & 63, part = tid >> 6;
        float s = 0.f, s2 = 0.f;
        #pragma unroll
        for (int i = 0; i < 32; i++) {
            float v = stats[c * 129 + part * 32 + i];
            s += v; s2 += v * v;
        }
        float* ps = (float*)(smem + OFF_PS);
        ps[part * 64 + c]       = s;
        ps[256 + part * 64 + c] = s2;
    }
    __syncthreads();
    if (tid < 64) {
        const float* ps = (const float*)(smem + OFF_PS);
        float S  = ps[tid] + ps[64 + tid] + ps[128 + tid] + ps[192 + tid];
        float S2 = ps[256 + tid] + ps[320 + tid] + ps[384 + tid] + ps[448 + tid];
        g_partials[blockIdx.x * 128 + tid]      = S;
        g_partials[blockIdx.x * 128 + 64 + tid] = S2;
    }
}

// ---------------- BN stats finalize ----------------
__global__ void bn_stats_kernel(const float* __restrict__ gamma, const float* __restrict__ beta) {
    __shared__ float sh[256];
    int tid = threadIdx.x;
    int c = tid & 127, seg = tid >> 7;
    const int half = (NTILES + 1) / 2;
    int lo = seg * half;
    int hi = lo + half; if (hi > NTILES) hi = NTILES;
    float s = 0.f;
    #pragma unroll 4
    for (int t = lo; t < hi; t++) s += g_partials[t * 128 + c];
    sh[tid] = s;
    __syncthreads();
    if (tid < 64) {
        float S  = sh[tid]      + sh[128 + tid];
        float S2 = sh[64 + tid] + sh[192 + tid];
        const float invN = 1.0f / (float)NROW;
        float mean = S * invN;
        float var  = S2 * invN - mean * mean;
        float inv  = rsqrtf(var + 1e-5f);
        float sc   = inv * gamma[tid];
        g_bn[tid]      = sc;
        g_bn[64 + tid] = beta[tid] - mean * sc;
    }
}

// ---------------- BN apply + ReLU ----------------
__global__ void bn_apply_kernel(float* __restrict__ out) {
    int i = blockIdx.x * 256 + threadIdx.x;
    if (i >= NROW * (COUT / 4)) return;
    int c = (i & 15) << 2;
    float4 v = reinterpret_cast<const float4*>(g_conv)[i];
    float4 r;
    r.x = fmaxf(fmaf(v.x, __ldg(&g_bn[c + 0]), __ldg(&g_bn[64 + c + 0])), 0.f);
    r.y = fmaxf(fmaf(v.y, __ldg(&g_bn[c + 1]), __ldg(&g_bn[64 + c + 1])), 0.f);
    r.z = fmaxf(fmaf(v.z, __ldg(&g_bn[c + 2]), __ldg(&g_bn[64 + c + 2])), 0.f);
    r.w = fmaxf(fmaf(v.w, __ldg(&g_bn[c + 3]), __ldg(&g_bn[64 + c + 3])), 0.f);
    reinterpret_cast<float4*>(out)[i] = r;
}

// ---------------- launch ----------------
extern "C" void kernel_launch(void* const* d_in, const int* in_sizes, int n_in,
                              void* d_out, int out_size) {
    const float* feats = (const float*)d_in[0];
    const float* W     = (const float*)d_in[1];
    const float* gamma = (const float*)d_in[2];
    const float* beta  = (const float*)d_in[3];
    const int*   nbr   = (const int*)d_in[4];
    const int*   mask  = (const int*)d_in[5];
    float* out = (float*)d_out;

    cudaFuncSetAttribute(conv_mma_kernel, cudaFuncAttributeMaxDynamicSharedMemorySize, SMEM_BYTES);

    prep_feats_kernel<<<(NROW * (CIN / 4) + (CIN / 4) + 255) / 256, 256>>>(feats);
    prep_w_kernel<<<(KOFF * CIN * COUT + 255) / 256, 256>>>(W);
    prep_idx_kernel<<<(KOFF * NROW + 255) / 256, 256>>>(nbr, mask);
    conv_mma_kernel<<<NTILES, 256, SMEM_BYTES>>>();
    bn_stats_kernel<<<1, 256>>>(gamma, beta);
    bn_apply_kernel<<<(NROW * (COUT / 4) + 255) / 256, 256>>>(out);
}

// round 8
// speedup vs baseline: 1.0667x; 1.0667x over previous
#include <cuda_runtime.h>
#include <cuda_fp16.h>
#include <cstdint>
#include <cstddef>

#define NROW   200000
#define CIN    64
#define COUT   64
#define KOFF   27
#define TILE_M 128
#define NTILES ((NROW + TILE_M - 1) / TILE_M)   // 1563

typedef unsigned long long u64t;

// ---------------- device scratch ----------------
__device__ __align__(128) __half g_feats16[(NROW + 8) * CIN];   // row NROW = zeros (tensor)
__device__ __align__(128) float  g_feats32[(NROW + 8) * CIN];   // row NROW = zeros (SIMT)
__device__ __align__(128) __half g_w16[KOFF * CIN * COUT];      // fp16 [k][cin][cout]
__device__ __align__(128) float  g_wT32[KOFF * COUT * CIN];     // fp32 [k][cout][cin]
__device__ int    g_idx2[KOFF * NROW];
__device__ float  g_conv[(size_t)NROW * COUT];
__device__ float  g_partials[NTILES * 128];
__device__ float  g_bn[128];

// ---------------- helpers ----------------
__device__ __forceinline__ uint32_t smem_u32(const void* p) {
    uint32_t a;
    asm("{ .reg .u64 t; cvta.to.shared.u64 t, %1; cvt.u32.u64 %0, t; }" : "=r"(a) : "l"(p));
    return a;
}
__device__ __forceinline__ void cp_async16(uint32_t dst, const void* src) {
    asm volatile("cp.async.cg.shared.global [%0], [%1], 16;" :: "r"(dst), "l"(src));
}
__device__ __forceinline__ void cp_commit() {
    asm volatile("cp.async.commit_group;" ::: "memory");
}
__device__ __forceinline__ void ldmatrix_x4(uint32_t* r, uint32_t addr) {
    asm volatile("ldmatrix.sync.aligned.m8n8.x4.shared.b16 {%0,%1,%2,%3}, [%4];"
                 : "=r"(r[0]), "=r"(r[1]), "=r"(r[2]), "=r"(r[3]) : "r"(addr));
}
__device__ __forceinline__ void ldmatrix_x4_t(uint32_t* r, uint32_t addr) {
    asm volatile("ldmatrix.sync.aligned.m8n8.x4.trans.shared.b16 {%0,%1,%2,%3}, [%4];"
                 : "=r"(r[0]), "=r"(r[1]), "=r"(r[2]), "=r"(r[3]) : "r"(addr));
}
__device__ __forceinline__ void mma16816(float* d, const uint32_t* a, uint32_t b0, uint32_t b1) {
    asm volatile(
        "mma.sync.aligned.m16n8k16.row.col.f32.f16.f16.f32 "
        "{%0,%1,%2,%3}, {%4,%5,%6,%7}, {%8,%9}, {%0,%1,%2,%3};"
        : "+f"(d[0]), "+f"(d[1]), "+f"(d[2]), "+f"(d[3])
        : "r"(a[0]), "r"(a[1]), "r"(a[2]), "r"(a[3]), "r"(b0), "r"(b1));
}
// non-volatile: schedulable, dependency-tracked through operands
#define FMA2(acc, a, w) asm("fma.rn.f32x2 %0, %1, %2, %0;" : "+l"(acc) : "l"(a), "l"(w))

// ---------------- SMEM layout ----------------
// tensor CTA:
#define TA_STRIDE 144
#define TA_STAGE  (128 * TA_STRIDE)   // 18432
#define TB_STRIDE 144
#define TB_STAGE  (64 * TB_STRIDE)    // 9216
#define OFF_TA    0
#define OFF_TB    (2 * TA_STAGE)      // 36864
// SIMT CTA:
#define SA_STRIDE 272                 // 64 f32 + 16B pad
#define SA_STAGE  (128 * SA_STRIDE)   // 34816
#define SW_STAGE  16384               // [q][cout][16B]: q*1024 + cout*16
#define OFF_SA    0
#define OFF_SW    (2 * SA_STAGE)      // 69632
#define SMEM_BYTES (OFF_SW + 2 * SW_STAGE)  // 102400
#define OFF_PS    34816               // epilogue partial sums (stats occupy [0,33024))

// ---------------- prep kernels ----------------
__global__ void prep_feats_kernel(const float* __restrict__ feats) {
    int i = blockIdx.x * 256 + threadIdx.x;
    if (i < NROW * (CIN / 4)) {
        float4 v = reinterpret_cast<const float4*>(feats)[i];
        __half2* dst = reinterpret_cast<__half2*>(g_feats16);
        dst[i * 2]     = __floats2half2_rn(v.x, v.y);
        dst[i * 2 + 1] = __floats2half2_rn(v.z, v.w);
        reinterpret_cast<float4*>(g_feats32)[i] = v;
    } else if (i < NROW * (CIN / 4) + (CIN / 4)) {
        __half2 z = __float2half2_rn(0.0f);
        __half2* dst = reinterpret_cast<__half2*>(g_feats16);
        dst[i * 2]     = z;
        dst[i * 2 + 1] = z;
        reinterpret_cast<float4*>(g_feats32)[i] = make_float4(0.f, 0.f, 0.f, 0.f);
    }
}
__global__ void prep_w_kernel(const float* __restrict__ W) {
    int i = blockIdx.x * 256 + threadIdx.x;
    if (i < KOFF * CIN * COUT) {
        int k  = i / (CIN * COUT);
        int r  = i % (CIN * COUT);
        int ci = r / COUT;
        int co = r % COUT;
        float w = W[i];
        g_w16[i] = __float2half_rn(w);
        g_wT32[(k * COUT + co) * CIN + ci] = w;
    }
}
__global__ void prep_idx_kernel(const int* __restrict__ nbr, const int* __restrict__ mask) {
    int i = blockIdx.x * 256 + threadIdx.x;
    if (i < KOFF * NROW) g_idx2[i] = mask[i] ? nbr[i] : NROW;
}

// ---------------- tensor-CTA loader ----------------
__device__ __forceinline__ void t_load_stage(uint32_t sb, int tid, int m0, int k) {
    int s = k & 1;
    uint32_t abuf = sb + OFF_TA + s * TA_STAGE;
    uint32_t bbuf = sb + OFF_TB + s * TB_STAGE;
    const int* idxk = g_idx2 + k * NROW;
    #pragma unroll
    for (int it = 0; it < 4; it++) {
        int cid = it * 256 + tid;
        int r = cid >> 3, ch = cid & 7;
        int m = m0 + r;
        int src = (m < NROW) ? __ldg(idxk + m) : NROW;
        cp_async16(abuf + (uint32_t)(r * TA_STRIDE + ch * 16),
                   (const char*)g_feats16 + ((size_t)src * (CIN * 2) + ch * 16));
    }
    const char* wsrc = (const char*)g_w16 + (size_t)k * (CIN * COUT * 2);
    #pragma unroll
    for (int it = 0; it < 2; it++) {
        int cid = it * 256 + tid;
        int r = cid >> 3, ch = cid & 7;
        cp_async16(bbuf + (uint32_t)(r * TB_STRIDE + ch * 16), wsrc + r * 128 + ch * 16);
    }
    cp_commit();
}

// ---------------- SIMT-CTA loader ----------------
__device__ __forceinline__ void s_load_stage(uint32_t sb, int tid, int m0, int k, int buf) {
    uint32_t abuf = sb + OFF_SA + buf * SA_STAGE;
    const int* idxk = g_idx2 + k * NROW;
    int ch = tid & 15;
    #pragma unroll
    for (int it = 0; it < 8; it++) {   // A: 128 rows x 16 x 16B (fp32)
        int r = it * 16 + (tid >> 4);
        int m = m0 + r;
        int src = (m < NROW) ? __ldg(idxk + m) : NROW;
        cp_async16(abuf + (uint32_t)(r * SA_STRIDE + ch * 16),
                   (const char*)g_feats32 + ((size_t)src * 256 + ch * 16));
    }
    uint32_t wbuf = sb + OFF_SW + buf * SW_STAGE;
    const char* wsrc = (const char*)g_wT32 + (size_t)k * (COUT * CIN * 4);
    #pragma unroll
    for (int it = 0; it < 4; it++) {   // W: [q][cout][16B], 1024 chunks
        int id = it * 256 + tid;
        int q = id >> 6, co = id & 63;
        cp_async16(wbuf + (uint32_t)(q * 1024 + co * 16), wsrc + co * 256 + q * 16);
    }
    cp_commit();
}

// ---------------- main kernel: CTA-specialized ----------------
__global__ void __launch_bounds__(256, 2) conv_mma_kernel() {
    extern __shared__ char smem[];
    uint32_t sb = smem_u32(smem);
    int tid = threadIdx.x;
    int m0 = blockIdx.x * TILE_M;
    float* stats = (float*)smem;   // [64][129] f32, written post-compute
    bool tensor_cta = (blockIdx.x & 7) < 3;   // 3/8 tensor

    if (tensor_cta) {
        // ============ TENSOR CTA (R2-proven) ============
        int lane = tid & 31, wid = tid >> 5;
        int warp_m = wid & 3, warp_n = wid >> 2;
        float d[2][4][4];
        #pragma unroll
        for (int i = 0; i < 2; i++)
            #pragma unroll
            for (int j = 0; j < 4; j++)
                #pragma unroll
                for (int l = 0; l < 4; l++) d[i][j][l] = 0.f;

        t_load_stage(sb, tid, m0, 0);
        uint32_t a_off = (uint32_t)((warp_m * 32 + (lane & 15)) * TA_STRIDE + (lane >> 4) * 16);
        uint32_t b_off = (uint32_t)((lane & 15) * TB_STRIDE + warp_n * 64 + (lane >> 4) * 16);

        #pragma unroll 1
        for (int k = 0; k < KOFF; k++) {
            if (k < KOFF - 1) {
                t_load_stage(sb, tid, m0, k + 1);
                asm volatile("cp.async.wait_group 1;" ::: "memory");
            } else {
                asm volatile("cp.async.wait_group 0;" ::: "memory");
            }
            __syncthreads();
            uint32_t abase = sb + OFF_TA + (k & 1) * TA_STAGE + a_off;
            uint32_t bbase = sb + OFF_TB + (k & 1) * TB_STAGE + b_off;
            #pragma unroll
            for (int kk = 0; kk < 4; kk++) {
                uint32_t a0 = abase + kk * 32;
                uint32_t bk = bbase + kk * 16 * TB_STRIDE;
                uint32_t afr[2][4], bfr[2][4];
                ldmatrix_x4(afr[0], a0);
                ldmatrix_x4(afr[1], a0 + 16 * TA_STRIDE);
                ldmatrix_x4_t(bfr[0], bk);
                ldmatrix_x4_t(bfr[1], bk + 32);
                #pragma unroll
                for (int mi = 0; mi < 2; mi++)
                    #pragma unroll
                    for (int nn = 0; nn < 4; nn++)
                        mma16816(d[mi][nn], afr[mi],
                                 bfr[nn >> 1][(nn & 1) * 2], bfr[nn >> 1][(nn & 1) * 2 + 1]);
            }
            __syncthreads();
        }
        {
            int r0 = warp_m * 32 + (lane >> 2);
            int c0 = warp_n * 32 + (lane & 3) * 2;
            #pragma unroll
            for (int mi = 0; mi < 2; mi++)
                #pragma unroll
                for (int nn = 0; nn < 4; nn++) {
                    int r = r0 + mi * 16;
                    int c = c0 + nn * 8;
                    stats[(c + 0) * 129 + r]     = d[mi][nn][0];
                    stats[(c + 1) * 129 + r]     = d[mi][nn][1];
                    stats[(c + 0) * 129 + r + 8] = d[mi][nn][2];
                    stats[(c + 1) * 129 + r + 8] = d[mi][nn][3];
                }
        }
    } else {
        // ============ SIMT CTA: fma.rn.f32x2, wavefront-economical ============
        // warp w: rows [16w,16w+16); lane: rg=lane&3, cg=lane>>2
        int lane = tid & 31, wid = tid >> 5;
        int rg = lane & 3, cg = lane >> 2;
        u64t acc[4][8];
        #pragma unroll
        for (int j = 0; j < 4; j++)
            #pragma unroll
            for (int c = 0; c < 8; c++) acc[j][c] = 0ull;

        s_load_stage(sb, tid, m0, 0, 0);
        s_load_stage(sb, tid, m0, 1, 1);

        const char* sa_t = smem + (size_t)((wid * 16 + rg) * SA_STRIDE);
        const char* sw_t = smem + (size_t)(OFF_SW + cg * 16);

        #pragma unroll 1
        for (int k = 0; k < KOFF; k++) {
            if (k < KOFF - 1) asm volatile("cp.async.wait_group 1;" ::: "memory");
            else              asm volatile("cp.async.wait_group 0;" ::: "memory");
            __syncthreads();

            const char* sa = sa_t + (k & 1) * SA_STAGE;
            const char* sw = sw_t + (k & 1) * SW_STAGE;
            #pragma unroll 2
            for (int q = 0; q < 16; q++) {
                ulonglong2 a0 = *(const ulonglong2*)(sa + q * 16);
                ulonglong2 a1 = *(const ulonglong2*)(sa + 4 * SA_STRIDE + q * 16);
                ulonglong2 a2 = *(const ulonglong2*)(sa + 8 * SA_STRIDE + q * 16);
                ulonglong2 a3 = *(const ulonglong2*)(sa + 12 * SA_STRIDE + q * 16);
                #pragma unroll
                for (int h = 0; h < 2; h++) {
                    const char* swq = sw + q * 1024 + h * 512;
                    ulonglong2 w0 = *(const ulonglong2*)(swq);
                    ulonglong2 w1 = *(const ulonglong2*)(swq + 128);
                    ulonglong2 w2 = *(const ulonglong2*)(swq + 256);
                    ulonglong2 w3 = *(const ulonglong2*)(swq + 384);
                    FMA2(acc[0][h*4+0], a0.x, w0.x); FMA2(acc[0][h*4+0], a0.y, w0.y);
                    FMA2(acc[0][h*4+1], a0.x, w1.x); FMA2(acc[0][h*4+1], a0.y, w1.y);
                    FMA2(acc[0][h*4+2], a0.x, w2.x); FMA2(acc[0][h*4+2], a0.y, w2.y);
                    FMA2(acc[0][h*4+3], a0.x, w3.x); FMA2(acc[0][h*4+3], a0.y, w3.y);
                    FMA2(acc[1][h*4+0], a1.x, w0.x); FMA2(acc[1][h*4+0], a1.y, w0.y);
                    FMA2(acc[1][h*4+1], a1.x, w1.x); FMA2(acc[1][h*4+1], a1.y, w1.y);
                    FMA2(acc[1][h*4+2], a1.x, w2.x); FMA2(acc[1][h*4+2], a1.y, w2.y);
                    FMA2(acc[1][h*4+3], a1.x, w3.x); FMA2(acc[1][h*4+3], a1.y, w3.y);
                    FMA2(acc[2][h*4+0], a2.x, w0.x); FMA2(acc[2][h*4+0], a2.y, w0.y);
                    FMA2(acc[2][h*4+1], a2.x, w1.x); FMA2(acc[2][h*4+1], a2.y, w1.y);
                    FMA2(acc[2][h*4+2], a2.x, w2.x); FMA2(acc[2][h*4+2], a2.y, w2.y);
                    FMA2(acc[2][h*4+3], a2.x, w3.x); FMA2(acc[2][h*4+3], a2.y, w3.y);
                    FMA2(acc[3][h*4+0], a3.x, w0.x); FMA2(acc[3][h*4+0], a3.y, w0.y);
                    FMA2(acc[3][h*4+1], a3.x, w1.x); FMA2(acc[3][h*4+1], a3.y, w1.y);
                    FMA2(acc[3][h*4+2], a3.x, w2.x); FMA2(acc[3][h*4+2], a3.y, w2.y);
                    FMA2(acc[3][h*4+3], a3.x, w3.x); FMA2(acc[3][h*4+3], a3.y, w3.y);
                }
            }
            __syncthreads();
            if (k + 2 < KOFF) s_load_stage(sb, tid, m0, k + 2, k & 1);
        }
        // horizontal add of cin-pair partials -> stats
        #pragma unroll
        for (int j = 0; j < 4; j++) {
            int r = wid * 16 + rg + 4 * j;
            #pragma unroll
            for (int c = 0; c < 8; c++) {
                uint32_t lo, hi;
                asm("mov.b64 {%0, %1}, %2;" : "=r"(lo), "=r"(hi) : "l"(acc[j][c]));
                stats[(cg + 8 * c) * 129 + r] = __uint_as_float(lo) + __uint_as_float(hi);
            }
        }
    }
    __syncthreads();

    // ---------------- common epilogue ----------------
    #pragma unroll
    for (int it = 0; it < 8; it++) {
        int idx = it * 256 + tid;
        int r = idx >> 4, c4 = idx & 15;
        int m = m0 + r;
        if (m < NROW) {
            float4 v;
            v.x = stats[(c4 * 4 + 0) * 129 + r];
            v.y = stats[(c4 * 4 + 1) * 129 + r];
            v.z = stats[(c4 * 4 + 2) * 129 + r];
            v.w = stats[(c4 * 4 + 3) * 129 + r];
            reinterpret_cast<float4*>(g_conv + (size_t)m * COUT)[c4] = v;
        }
    }
    {
        int c = tid & 63, part = tid >> 6;
        float s = 0.f, s2 = 0.f;
        #pragma unroll
        for (int i = 0; i < 32; i++) {
            float v = stats[c * 129 + part * 32 + i];
            s += v; s2 += v * v;
        }
        float* ps = (float*)(smem + OFF_PS);
        ps[part * 64 + c]       = s;
        ps[256 + part * 64 + c] = s2;
    }
    __syncthreads();
    if (tid < 64) {
        const float* ps = (const float*)(smem + OFF_PS);
        float S  = ps[tid] + ps[64 + tid] + ps[128 + tid] + ps[192 + tid];
        float S2 = ps[256 + tid] + ps[320 + tid] + ps[384 + tid] + ps[448 + tid];
        g_partials[blockIdx.x * 128 + tid]      = S;
        g_partials[blockIdx.x * 128 + 64 + tid] = S2;
    }
}

// ---------------- BN stats finalize ----------------
__global__ void bn_stats_kernel(const float* __restrict__ gamma, const float* __restrict__ beta) {
    __shared__ float sh[256];
    int tid = threadIdx.x;
    int c = tid & 127, seg = tid >> 7;
    const int half = (NTILES + 1) / 2;
    int lo = seg * half;
    int hi = lo + half; if (hi > NTILES) hi = NTILES;
    float s = 0.f;
    #pragma unroll 4
    for (int t = lo; t < hi; t++) s += g_partials[t * 128 + c];
    sh[tid] = s;
    __syncthreads();
    if (tid < 64) {
        float S  = sh[tid]      + sh[128 + tid];
        float S2 = sh[64 + tid] + sh[192 + tid];
        const float invN = 1.0f / (float)NROW;
        float mean = S * invN;
        float var  = S2 * invN - mean * mean;
        float inv  = rsqrtf(var + 1e-5f);
        float sc   = inv * gamma[tid];
        g_bn[tid]      = sc;
        g_bn[64 + tid] = beta[tid] - mean * sc;
    }
}

// ---------------- BN apply + ReLU ----------------
__global__ void bn_apply_kernel(float* __restrict__ out) {
    int i = blockIdx.x * 256 + threadIdx.x;
    if (i >= NROW * (COUT / 4)) return;
    int c = (i & 15) << 2;
    float4 v = reinterpret_cast<const float4*>(g_conv)[i];
    float4 r;
    r.x = fmaxf(fmaf(v.x, __ldg(&g_bn[c + 0]), __ldg(&g_bn[64 + c + 0])), 0.f);
    r.y = fmaxf(fmaf(v.y, __ldg(&g_bn[c + 1]), __ldg(&g_bn[64 + c + 1])), 0.f);
    r.z = fmaxf(fmaf(v.z, __ldg(&g_bn[c + 2]), __ldg(&g_bn[64 + c + 2])), 0.f);
    r.w = fmaxf(fmaf(v.w, __ldg(&g_bn[c + 3]), __ldg(&g_bn[64 + c + 3])), 0.f);
    reinterpret_cast<float4*>(out)[i] = r;
}

// ---------------- launch ----------------
extern "C" void kernel_launch(void* const* d_in, const int* in_sizes, int n_in,
                              void* d_out, int out_size) {
    const float* feats = (const float*)d_in[0];
    const float* W     = (const float*)d_in[1];
    const float* gamma = (const float*)d_in[2];
    const float* beta  = (const float*)d_in[3];
    const int*   nbr   = (const int*)d_in[4];
    const int*   mask  = (const int*)d_in[5];
    float* out = (float*)d_out;

    cudaFuncSetAttribute(conv_mma_kernel, cudaFuncAttributeMaxDynamicSharedMemorySize, SMEM_BYTES);

    prep_feats_kernel<<<(NROW * (CIN / 4) + (CIN / 4) + 255) / 256, 256>>>(feats);
    prep_w_kernel<<<(KOFF * CIN * COUT + 255) / 256, 256>>>(W);
    prep_idx_kernel<<<(KOFF * NROW + 255) / 256, 256>>>(nbr, mask);
    conv_mma_kernel<<<NTILES, 256, SMEM_BYTES>>>();
    bn_stats_kernel<<<1, 256>>>(gamma, beta);
    bn_apply_kernel<<<(NROW * (COUT / 4) + 255) / 256, 256>>>(out);
}

// round 10
// speedup vs baseline: 1.1041x; 1.0350x over previous
#include <cuda_runtime.h>
#include <cuda_fp16.h>
#include <cstdint>
#include <cstddef>

#define NROW   200000
#define CIN    64
#define COUT   64
#define KOFF   27
#define TILE_M 128
#define NTILES ((NROW + TILE_M - 1) / TILE_M)   // 1563

typedef unsigned long long u64t;

// ---------------- device scratch ----------------
__device__ __align__(128) __half g_feats16[(NROW + 8) * CIN];   // row NROW = zeros (tensor)
__device__ __align__(128) float  g_feats32[(NROW + 8) * CIN];   // row NROW = zeros (SIMT)
__device__ __align__(128) __half g_w16[KOFF * CIN * COUT];      // fp16 [k][cin][cout]
__device__ __align__(128) float  g_wf32[KOFF * CIN * COUT];     // fp32 [k][cin][cout] (natural)
__device__ int    g_idx2[KOFF * NROW];
__device__ float  g_conv[(size_t)NROW * COUT];
__device__ float  g_partials[NTILES * 128];
__device__ float  g_bn[128];

// ---------------- helpers ----------------
__device__ __forceinline__ uint32_t smem_u32(const void* p) {
    uint32_t a;
    asm("{ .reg .u64 t; cvta.to.shared.u64 t, %1; cvt.u32.u64 %0, t; }" : "=r"(a) : "l"(p));
    return a;
}
__device__ __forceinline__ void cp_async16(uint32_t dst, const void* src) {
    asm volatile("cp.async.cg.shared.global [%0], [%1], 16;" :: "r"(dst), "l"(src));
}
__device__ __forceinline__ void cp_commit() {
    asm volatile("cp.async.commit_group;" ::: "memory");
}
__device__ __forceinline__ void ldmatrix_x4(uint32_t* r, uint32_t addr) {
    asm volatile("ldmatrix.sync.aligned.m8n8.x4.shared.b16 {%0,%1,%2,%3}, [%4];"
                 : "=r"(r[0]), "=r"(r[1]), "=r"(r[2]), "=r"(r[3]) : "r"(addr));
}
__device__ __forceinline__ void ldmatrix_x4_t(uint32_t* r, uint32_t addr) {
    asm volatile("ldmatrix.sync.aligned.m8n8.x4.trans.shared.b16 {%0,%1,%2,%3}, [%4];"
                 : "=r"(r[0]), "=r"(r[1]), "=r"(r[2]), "=r"(r[3]) : "r"(addr));
}
__device__ __forceinline__ void mma16816(float* d, const uint32_t* a, uint32_t b0, uint32_t b1) {
    asm volatile(
        "mma.sync.aligned.m16n8k16.row.col.f32.f16.f16.f32 "
        "{%0,%1,%2,%3}, {%4,%5,%6,%7}, {%8,%9}, {%0,%1,%2,%3};"
        : "+f"(d[0]), "+f"(d[1]), "+f"(d[2]), "+f"(d[3])
        : "r"(a[0]), "r"(a[1]), "r"(a[2]), "r"(a[3]), "r"(b0), "r"(b1));
}
// non-volatile, schedulable
#define FMA2(acc, a, w) asm("fma.rn.f32x2 %0, %1, %2, %0;" : "+l"(acc) : "l"(a), "l"(w))
#define DUP(d, f)       asm("mov.b64 %0, {%1, %1};" : "=l"(d) : "r"(__float_as_uint(f)))

// ---------------- SMEM layout ----------------
// tensor CTA:
#define TA_STRIDE 144
#define TA_STAGE  (128 * TA_STRIDE)   // 18432
#define TB_STRIDE 144
#define TB_STAGE  (64 * TB_STRIDE)    // 9216
#define OFF_TA    0
#define OFF_TB    (2 * TA_STAGE)      // 36864
// SIMT CTA:
#define SA_STRIDE 272                 // 64 f32 + 16B pad
#define SA_STAGE  (128 * SA_STRIDE)   // 34816
#define SW_STAGE  16384               // W natural [cin][256B]
#define OFF_SA    0
#define OFF_SW    (2 * SA_STAGE)      // 69632
#define SMEM_BYTES (OFF_SW + 2 * SW_STAGE)  // 102400
#define OFF_PS    34816               // epilogue partial sums (stats occupy [0,33024))

// ---------------- prep kernels ----------------
__global__ void prep_feats_kernel(const float* __restrict__ feats) {
    int i = blockIdx.x * 256 + threadIdx.x;
    if (i < NROW * (CIN / 4)) {
        float4 v = reinterpret_cast<const float4*>(feats)[i];
        __half2* dst = reinterpret_cast<__half2*>(g_feats16);
        dst[i * 2]     = __floats2half2_rn(v.x, v.y);
        dst[i * 2 + 1] = __floats2half2_rn(v.z, v.w);
        reinterpret_cast<float4*>(g_feats32)[i] = v;
    } else if (i < NROW * (CIN / 4) + (CIN / 4)) {
        __half2 z = __float2half2_rn(0.0f);
        __half2* dst = reinterpret_cast<__half2*>(g_feats16);
        dst[i * 2]     = z;
        dst[i * 2 + 1] = z;
        reinterpret_cast<float4*>(g_feats32)[i] = make_float4(0.f, 0.f, 0.f, 0.f);
    }
}
__global__ void prep_w_kernel(const float* __restrict__ W) {
    int i = blockIdx.x * 256 + threadIdx.x;
    if (i < KOFF * CIN * COUT) {
        float w = W[i];
        g_w16[i]  = __float2half_rn(w);
        g_wf32[i] = w;                 // natural [k][cin][cout]
    }
}
__global__ void prep_idx_kernel(const int* __restrict__ nbr, const int* __restrict__ mask) {
    int i = blockIdx.x * 256 + threadIdx.x;
    if (i < KOFF * NROW) g_idx2[i] = mask[i] ? nbr[i] : NROW;
}

// ---------------- tensor-CTA loader ----------------
__device__ __forceinline__ void t_load_stage(uint32_t sb, int tid, int m0, int k) {
    int s = k & 1;
    uint32_t abuf = sb + OFF_TA + s * TA_STAGE;
    uint32_t bbuf = sb + OFF_TB + s * TB_STAGE;
    const int* idxk = g_idx2 + k * NROW;
    #pragma unroll
    for (int it = 0; it < 4; it++) {
        int cid = it * 256 + tid;
        int r = cid >> 3, ch = cid & 7;
        int m = m0 + r;
        int src = (m < NROW) ? __ldg(idxk + m) : NROW;
        cp_async16(abuf + (uint32_t)(r * TA_STRIDE + ch * 16),
                   (const char*)g_feats16 + ((size_t)src * (CIN * 2) + ch * 16));
    }
    const char* wsrc = (const char*)g_w16 + (size_t)k * (CIN * COUT * 2);
    #pragma unroll
    for (int it = 0; it < 2; it++) {
        int cid = it * 256 + tid;
        int r = cid >> 3, ch = cid & 7;
        cp_async16(bbuf + (uint32_t)(r * TB_STRIDE + ch * 16), wsrc + r * 128 + ch * 16);
    }
    cp_commit();
}

// ---------------- SIMT-CTA loader ----------------
__device__ __forceinline__ void s_load_stage(uint32_t sb, int tid, int m0, int k, int buf) {
    uint32_t abuf = sb + OFF_SA + buf * SA_STAGE;
    const int* idxk = g_idx2 + k * NROW;
    int ch = tid & 15;
    #pragma unroll
    for (int it = 0; it < 8; it++) {   // A: 128 rows x 16 x 16B (fp32)
        int r = it * 16 + (tid >> 4);
        int m = m0 + r;
        int src = (m < NROW) ? __ldg(idxk + m) : NROW;
        cp_async16(abuf + (uint32_t)(r * SA_STRIDE + ch * 16),
                   (const char*)g_feats32 + ((size_t)src * 256 + ch * 16));
    }
    uint32_t wbuf = sb + OFF_SW + buf * SW_STAGE;
    const char* wsrc = (const char*)g_wf32 + (size_t)k * (CIN * COUT * 4);
    #pragma unroll
    for (int it = 0; it < 4; it++) {   // W: straight 16KB copy, natural layout
        int id = it * 256 + tid;
        cp_async16(wbuf + (uint32_t)(id * 16), wsrc + id * 16);
    }
    cp_commit();
}

// ---------------- main kernel: CTA-specialized ----------------
__global__ void __launch_bounds__(256, 2) conv_mma_kernel() {
    extern __shared__ char smem[];
    uint32_t sb = smem_u32(smem);
    int tid = threadIdx.x;
    int m0 = blockIdx.x * TILE_M;
    float* stats = (float*)smem;   // [64][129] f32, written post-compute
    bool tensor_cta = (blockIdx.x & 7) < 3;   // 3/8 tensor

    if (tensor_cta) {
        // ============ TENSOR CTA (R2-proven) ============
        int lane = tid & 31, wid = tid >> 5;
        int warp_m = wid & 3, warp_n = wid >> 2;
        float d[2][4][4];
        #pragma unroll
        for (int i = 0; i < 2; i++)
            #pragma unroll
            for (int j = 0; j < 4; j++)
                #pragma unroll
                for (int l = 0; l < 4; l++) d[i][j][l] = 0.f;

        t_load_stage(sb, tid, m0, 0);
        uint32_t a_off = (uint32_t)((warp_m * 32 + (lane & 15)) * TA_STRIDE + (lane >> 4) * 16);
        uint32_t b_off = (uint32_t)((lane & 15) * TB_STRIDE + warp_n * 64 + (lane >> 4) * 16);

        #pragma unroll 1
        for (int k = 0; k < KOFF; k++) {
            if (k < KOFF - 1) {
                t_load_stage(sb, tid, m0, k + 1);
                asm volatile("cp.async.wait_group 1;" ::: "memory");
            } else {
                asm volatile("cp.async.wait_group 0;" ::: "memory");
            }
            __syncthreads();
            uint32_t abase = sb + OFF_TA + (k & 1) * TA_STAGE + a_off;
            uint32_t bbase = sb + OFF_TB + (k & 1) * TB_STAGE + b_off;
            #pragma unroll
            for (int kk = 0; kk < 4; kk++) {
                uint32_t a0 = abase + kk * 32;
                uint32_t bk = bbase + kk * 16 * TB_STRIDE;
                uint32_t afr[2][4], bfr[2][4];
                ldmatrix_x4(afr[0], a0);
                ldmatrix_x4(afr[1], a0 + 16 * TA_STRIDE);
                ldmatrix_x4_t(bfr[0], bk);
                ldmatrix_x4_t(bfr[1], bk + 32);
                #pragma unroll
                for (int mi = 0; mi < 2; mi++)
                    #pragma unroll
                    for (int nn = 0; nn < 4; nn++)
                        mma16816(d[mi][nn], afr[mi],
                                 bfr[nn >> 1][(nn & 1) * 2], bfr[nn >> 1][(nn & 1) * 2 + 1]);
            }
            __syncthreads();
        }
        {
            int r0 = warp_m * 32 + (lane >> 2);
            int c0 = warp_n * 32 + (lane & 3) * 2;
            #pragma unroll
            for (int mi = 0; mi < 2; mi++)
                #pragma unroll
                for (int nn = 0; nn < 4; nn++) {
                    int r = r0 + mi * 16;
                    int c = c0 + nn * 8;
                    stats[(c + 0) * 129 + r]     = d[mi][nn][0];
                    stats[(c + 1) * 129 + r]     = d[mi][nn][1];
                    stats[(c + 0) * 129 + r + 8] = d[mi][nn][2];
                    stats[(c + 1) * 129 + r + 8] = d[mi][nn][3];
                }
        }
    } else {
        // ============ SIMT CTA: cout-pair FFMA2, low-register ============
        // warp w: rows [16w,16w+16); lane: rg=lane&3 (row), cg=lane>>2 (8 couts)
        // thread: rows {16w+rg+4j, j=0..3}, couts [8cg, 8cg+8) as 4 pairs
        int lane = tid & 31, wid = tid >> 5;
        int rg = lane & 3, cg = lane >> 2;
        u64t acc[4][4];                 // [row j][cout pair p] -> 16 u64 = 32 regs
        #pragma unroll
        for (int j = 0; j < 4; j++)
            #pragma unroll
            for (int p = 0; p < 4; p++) acc[j][p] = 0ull;

        s_load_stage(sb, tid, m0, 0, 0);
        s_load_stage(sb, tid, m0, 1, 1);

        const char* sa_t = smem + (size_t)((wid * 16 + rg) * SA_STRIDE);
        const char* sw_t = smem + (size_t)(OFF_SW + cg * 32);

        #pragma unroll 1
        for (int k = 0; k < KOFF; k++) {
            if (k < KOFF - 1) asm volatile("cp.async.wait_group 1;" ::: "memory");
            else              asm volatile("cp.async.wait_group 0;" ::: "memory");
            __syncthreads();

            const char* sa = sa_t + (k & 1) * SA_STAGE;
            const char* sw = sw_t + (k & 1) * SW_STAGE;
            #pragma unroll 2
            for (int q = 0; q < 16; q++) {
                float4 a0 = *(const float4*)(sa + q * 16);
                float4 a1 = *(const float4*)(sa + 4 * SA_STRIDE + q * 16);
                float4 a2 = *(const float4*)(sa + 8 * SA_STRIDE + q * 16);
                float4 a3 = *(const float4*)(sa + 12 * SA_STRIDE + q * 16);
                #pragma unroll
                for (int c1 = 0; c1 < 4; c1++) {   // cin = 4q + c1
                    const char* swc = sw + (q * 4 + c1) * 256;
                    ulonglong2 wA = *(const ulonglong2*)(swc);        // couts 8cg+0..3
                    ulonglong2 wB = *(const ulonglong2*)(swc + 16);   // couts 8cg+4..7
                    float f0 = (c1 == 0) ? a0.x : (c1 == 1) ? a0.y : (c1 == 2) ? a0.z : a0.w;
                    float f1 = (c1 == 0) ? a1.x : (c1 == 1) ? a1.y : (c1 == 2) ? a1.z : a1.w;
                    float f2 = (c1 == 0) ? a2.x : (c1 == 1) ? a2.y : (c1 == 2) ? a2.z : a2.w;
                    float f3 = (c1 == 0) ? a3.x : (c1 == 1) ? a3.y : (c1 == 2) ? a3.z : a3.w;
                    u64t d0, d1, d2, d3;
                    DUP(d0, f0); DUP(d1, f1); DUP(d2, f2); DUP(d3, f3);
                    FMA2(acc[0][0], d0, wA.x); FMA2(acc[0][1], d0, wA.y);
                    FMA2(acc[0][2], d0, wB.x); FMA2(acc[0][3], d0, wB.y);
                    FMA2(acc[1][0], d1, wA.x); FMA2(acc[1][1], d1, wA.y);
                    FMA2(acc[1][2], d1, wB.x); FMA2(acc[1][3], d1, wB.y);
                    FMA2(acc[2][0], d2, wA.x); FMA2(acc[2][1], d2, wA.y);
                    FMA2(acc[2][2], d2, wB.x); FMA2(acc[2][3], d2, wB.y);
                    FMA2(acc[3][0], d3, wA.x); FMA2(acc[3][1], d3, wA.y);
                    FMA2(acc[3][2], d3, wB.x); FMA2(acc[3][3], d3, wB.y);
                }
            }
            __syncthreads();
            if (k + 2 < KOFF) s_load_stage(sb, tid, m0, k + 2, k & 1);
        }
        // unpack cout-pairs -> stats (each pair = two real outputs; no h-add)
        #pragma unroll
        for (int j = 0; j < 4; j++) {
            int r = wid * 16 + rg + 4 * j;
            #pragma unroll
            for (int p = 0; p < 4; p++) {
                uint32_t lo, hi;
                asm("mov.b64 {%0, %1}, %2;" : "=r"(lo), "=r"(hi) : "l"(acc[j][p]));
                stats[(cg * 8 + 2 * p + 0) * 129 + r] = __uint_as_float(lo);
                stats[(cg * 8 + 2 * p + 1) * 129 + r] = __uint_as_float(hi);
            }
        }
    }
    __syncthreads();

    // ---------------- common epilogue ----------------
    #pragma unroll
    for (int it = 0; it < 8; it++) {
        int idx = it * 256 + tid;
        int r = idx >> 4, c4 = idx & 15;
        int m = m0 + r;
        if (m < NROW) {
            float4 v;
            v.x = stats[(c4 * 4 + 0) * 129 + r];
            v.y = stats[(c4 * 4 + 1) * 129 + r];
            v.z = stats[(c4 * 4 + 2) * 129 + r];
            v.w = stats[(c4 * 4 + 3) * 129 + r];
            reinterpret_cast<float4*>(g_conv + (size_t)m * COUT)[c4] = v;
        }
    }
    {
        int c = tid & 63, part = tid >> 6;
        float s = 0.f, s2 = 0.f;
        #pragma unroll
        for (int i = 0; i < 32; i++) {
            float v = stats[c * 129 + part * 32 + i];
            s += v; s2 += v * v;
        }
        float* ps = (float*)(smem + OFF_PS);
        ps[part * 64 + c]       = s;
        ps[256 + part * 64 + c] = s2;
    }
    __syncthreads();
    if (tid < 64) {
        const float* ps = (const float*)(smem + OFF_PS);
        float S  = ps[tid] + ps[64 + tid] + ps[128 + tid] + ps[192 + tid];
        float S2 = ps[256 + tid] + ps[320 + tid] + ps[384 + tid] + ps[448 + tid];
        g_partials[blockIdx.x * 128 + tid]      = S;
        g_partials[blockIdx.x * 128 + 64 + tid] = S2;
    }
}

// ---------------- BN stats finalize ----------------
__global__ void bn_stats_kernel(const float* __restrict__ gamma, const float* __restrict__ beta) {
    __shared__ float sh[256];
    int tid = threadIdx.x;
    int c = tid & 127, seg = tid >> 7;
    const int half = (NTILES + 1) / 2;
    int lo = seg * half;
    int hi = lo + half; if (hi > NTILES) hi = NTILES;
    float s = 0.f;
    #pragma unroll 4
    for (int t = lo; t < hi; t++) s += g_partials[t * 128 + c];
    sh[tid] = s;
    __syncthreads();
    if (tid < 64) {
        float S  = sh[tid]      + sh[128 + tid];
        float S2 = sh[64 + tid] + sh[192 + tid];
        const float invN = 1.0f / (float)NROW;
        float mean = S * invN;
        float var  = S2 * invN - mean * mean;
        float inv  = rsqrtf(var + 1e-5f);
        float sc   = inv * gamma[tid];
        g_bn[tid]      = sc;
        g_bn[64 + tid] = beta[tid] - mean * sc;
    }
}

// ---------------- BN apply + ReLU ----------------
__global__ void bn_apply_kernel(float* __restrict__ out) {
    int i = blockIdx.x * 256 + threadIdx.x;
    if (i >= NROW * (COUT / 4)) return;
    int c = (i & 15) << 2;
    float4 v = reinterpret_cast<const float4*>(g_conv)[i];
    float4 r;
    r.x = fmaxf(fmaf(v.x, __ldg(&g_bn[c + 0]), __ldg(&g_bn[64 + c + 0])), 0.f);
    r.y = fmaxf(fmaf(v.y, __ldg(&g_bn[c + 1]), __ldg(&g_bn[64 + c + 1])), 0.f);
    r.z = fmaxf(fmaf(v.z, __ldg(&g_bn[c + 2]), __ldg(&g_bn[64 + c + 2])), 0.f);
    r.w = fmaxf(fmaf(v.w, __ldg(&g_bn[c + 3]), __ldg(&g_bn[64 + c + 3])), 0.f);
    reinterpret_cast<float4*>(out)[i] = r;
}

// ---------------- launch ----------------
extern "C" void kernel_launch(void* const* d_in, const int* in_sizes, int n_in,
                              void* d_out, int out_size) {
    const float* feats = (const float*)d_in[0];
    const float* W     = (const float*)d_in[1];
    const float* gamma = (const float*)d_in[2];
    const float* beta  = (const float*)d_in[3];
    const int*   nbr   = (const int*)d_in[4];
    const int*   mask  = (const int*)d_in[5];
    float* out = (float*)d_out;

    cudaFuncSetAttribute(conv_mma_kernel, cudaFuncAttributeMaxDynamicSharedMemorySize, SMEM_BYTES);

    prep_feats_kernel<<<(NROW * (CIN / 4) + (CIN / 4) + 255) / 256, 256>>>(feats);
    prep_w_kernel<<<(KOFF * CIN * COUT + 255) / 256, 256>>>(W);
    prep_idx_kernel<<<(KOFF * NROW + 255) / 256, 256>>>(nbr, mask);
    conv_mma_kernel<<<NTILES, 256, SMEM_BYTES>>>();
    bn_stats_kernel<<<1, 256>>>(gamma, beta);
    bn_apply_kernel<<<(NROW * (COUT / 4) + 255) / 256, 256>>>(out);
}